// round 3
// baseline (speedup 1.0000x reference)
#include <cuda_runtime.h>

// ---------------------------------------------------------------------------
// GATv2 layer, fused 4-kernel pipeline:
//   K0 zero_kernel : clear agg + seg_sum scratch
//   K1 sgemm_proj  : proj[N,384] = X @ [Wl|Wr|Wv] + [bl|br|bv]   (fp32 SGEMM)
//   K2 edge_kernel : ONE pass over edges:
//                      score = a.LeakyReLU(left[t]+right[s]) + ef@We + be
//                      e = exp(score)  (no segment-max needed: scores bounded)
//                      seg_sum[t,h] += e ;  agg[t,:] += e * values[s,:]
//   K3 sgemm_out   : out = (agg / seg_sum) @ Wo + bo  (normalize fused in A load)
// ---------------------------------------------------------------------------

#define N_MAX 50048
#define IN_F  256

__device__ float g_proj[(size_t)N_MAX * 384];  // [N][left 0:128 | right 128:256 | values 256:384]
__device__ float g_agg [(size_t)N_MAX * 128];
__device__ float g_sum [(size_t)N_MAX * 8];

// ------------------------------- K0: zero --------------------------------
__global__ void __launch_bounds__(256) zero_kernel(int n_nodes) {
    int stride = gridDim.x * blockDim.x;
    int idx = blockIdx.x * blockDim.x + threadIdx.x;
    int nAgg4 = n_nodes * 32;  // n*128 floats / 4
    float4 z = make_float4(0.f, 0.f, 0.f, 0.f);
    for (int i = idx; i < nAgg4; i += stride)
        reinterpret_cast<float4*>(g_agg)[i] = z;
    int nSum = n_nodes * 8;
    for (int i = idx; i < nSum; i += stride)
        g_sum[i] = 0.f;
}

// --------------------------- K1: projection GEMM --------------------------
// C[128x128] block per CTA, 256 threads, 8x8 micro-tile, BK=8.
// blockIdx.y selects which of the 3 weight matrices (output column band).
__global__ void __launch_bounds__(256, 2) sgemm_proj(
    const float* __restrict__ X,
    const float* __restrict__ Wl, const float* __restrict__ bl,
    const float* __restrict__ Wr, const float* __restrict__ br,
    const float* __restrict__ Wv, const float* __restrict__ bv,
    int M)
{
    const float* B;
    const float* bias;
    if (blockIdx.y == 0)      { B = Wl; bias = bl; }
    else if (blockIdx.y == 1) { B = Wr; bias = br; }
    else                      { B = Wv; bias = bv; }

    __shared__ float As[8][128];   // transposed A tile
    __shared__ float Bs[8][128];

    const int tid  = threadIdx.x;
    const int tx   = tid & 15;
    const int ty   = tid >> 4;
    const int rowBase = blockIdx.x * 128;
    const int aRow = tid >> 1;
    const int aCol = (tid & 1) * 4;
    const int bRow = tid >> 5;
    const int bCol = (tid & 31) * 4;
    const int gRow = rowBase + aRow;
    const bool aValid = (gRow < M);
    const float* Aptr = X + (size_t)gRow * IN_F;

    float acc[8][8];
#pragma unroll
    for (int i = 0; i < 8; i++)
#pragma unroll
        for (int j = 0; j < 8; j++) acc[i][j] = 0.f;

    for (int kk = 0; kk < IN_F; kk += 8) {
        float4 a4 = aValid ? *reinterpret_cast<const float4*>(Aptr + kk + aCol)
                           : make_float4(0.f, 0.f, 0.f, 0.f);
        As[aCol + 0][aRow] = a4.x;
        As[aCol + 1][aRow] = a4.y;
        As[aCol + 2][aRow] = a4.z;
        As[aCol + 3][aRow] = a4.w;
        float4 b4 = *reinterpret_cast<const float4*>(B + (size_t)(kk + bRow) * 128 + bCol);
        *reinterpret_cast<float4*>(&Bs[bRow][bCol]) = b4;
        __syncthreads();
#pragma unroll
        for (int k = 0; k < 8; k++) {
            float4 a0 = *reinterpret_cast<const float4*>(&As[k][ty * 8]);
            float4 a1 = *reinterpret_cast<const float4*>(&As[k][ty * 8 + 4]);
            float4 b0 = *reinterpret_cast<const float4*>(&Bs[k][tx * 8]);
            float4 b1 = *reinterpret_cast<const float4*>(&Bs[k][tx * 8 + 4]);
            float ra[8] = {a0.x, a0.y, a0.z, a0.w, a1.x, a1.y, a1.z, a1.w};
            float rb[8] = {b0.x, b0.y, b0.z, b0.w, b1.x, b1.y, b1.z, b1.w};
#pragma unroll
            for (int i = 0; i < 8; i++)
#pragma unroll
                for (int j = 0; j < 8; j++)
                    acc[i][j] = fmaf(ra[i], rb[j], acc[i][j]);
        }
        __syncthreads();
    }

    float bv8[8];
#pragma unroll
    for (int j = 0; j < 8; j++) bv8[j] = bias[tx * 8 + j];

#pragma unroll
    for (int i = 0; i < 8; i++) {
        int row = rowBase + ty * 8 + i;
        if (row < M) {
            float* cp = g_proj + (size_t)row * 384 + blockIdx.y * 128 + tx * 8;
            float4 o0 = make_float4(acc[i][0] + bv8[0], acc[i][1] + bv8[1],
                                    acc[i][2] + bv8[2], acc[i][3] + bv8[3]);
            float4 o1 = make_float4(acc[i][4] + bv8[4], acc[i][5] + bv8[5],
                                    acc[i][6] + bv8[6], acc[i][7] + bv8[7]);
            *reinterpret_cast<float4*>(cp)     = o0;
            *reinterpret_cast<float4*>(cp + 4) = o1;
        }
    }
}

// ------------------------------ K2: edge pass ------------------------------
// One warp handles one edge per loop iteration.
// Lane layout: head h = lane>>2, chunk = lane&3; lane owns dims [4*lane, 4*lane+4)
// of the flattened [H*D]=128 vector, i.e. 4 of head h's 16 dims.
// Per-head reduction = butterfly over the 4-lane group (xor 1, xor 2).
// Edge-bias weights We[:,h] are constant per lane -> hoisted to registers.
__global__ void __launch_bounds__(256) edge_kernel(
    const int*   __restrict__ ei, const float* __restrict__ ef,
    const float* __restrict__ We, const float* __restrict__ be,
    const float* __restrict__ av, int E)
{
    const int tid   = threadIdx.x;
    const int lane  = tid & 31;
    const int h     = lane >> 2;
    const int chunk = lane & 3;
    const int i0    = lane << 2;

    // loop-invariant per-lane constants
    float4 A4 = *reinterpret_cast<const float4*>(av + i0);
    float beh = be[h];
    float w[16];
#pragma unroll
    for (int j = 0; j < 16; j++)
        w[j] = We[(chunk * 16 + j) * 8 + h];

    int gw = (blockIdx.x * 256 + tid) >> 5;
    int nw = (gridDim.x * 256) >> 5;

    for (int e = gw; e < E; e += nw) {
        int s = __ldg(ei + e);
        int t = __ldg(ei + E + e);
        const float* baseT = g_proj + (size_t)t * 384;
        const float* baseS = g_proj + (size_t)s * 384;
        // issue all loads up front for MLP
        float4 L = *reinterpret_cast<const float4*>(baseT + i0);         // left[t]
        float4 R = *reinterpret_cast<const float4*>(baseS + 128 + i0);   // right[s]
        float4 V = *reinterpret_cast<const float4*>(baseS + 256 + i0);   // values[s]
        const float4* pe = reinterpret_cast<const float4*>(ef + (size_t)e * 64 + chunk * 16);
        float4 e0 = __ldg(pe + 0);
        float4 e1 = __ldg(pe + 1);
        float4 e2 = __ldg(pe + 2);
        float4 e3 = __ldg(pe + 3);

        float cx = L.x + R.x; cx = cx > 0.f ? cx : 0.2f * cx;
        float cy = L.y + R.y; cy = cy > 0.f ? cy : 0.2f * cy;
        float cz = L.z + R.z; cz = cz > 0.f ? cz : 0.2f * cz;
        float cw = L.w + R.w; cw = cw > 0.f ? cw : 0.2f * cw;
        float p = cx * A4.x + cy * A4.y + cz * A4.z + cw * A4.w;

        // edge-feature bias contribution (this lane's 16 of 64 features)
        p = fmaf(e0.x, w[0],  p); p = fmaf(e0.y, w[1],  p);
        p = fmaf(e0.z, w[2],  p); p = fmaf(e0.w, w[3],  p);
        p = fmaf(e1.x, w[4],  p); p = fmaf(e1.y, w[5],  p);
        p = fmaf(e1.z, w[6],  p); p = fmaf(e1.w, w[7],  p);
        p = fmaf(e2.x, w[8],  p); p = fmaf(e2.y, w[9],  p);
        p = fmaf(e2.z, w[10], p); p = fmaf(e2.w, w[11], p);
        p = fmaf(e3.x, w[12], p); p = fmaf(e3.y, w[13], p);
        p = fmaf(e3.z, w[14], p); p = fmaf(e3.w, w[15], p);

        // reduce over the 4-lane head group
        p += __shfl_xor_sync(0xffffffffu, p, 1);
        p += __shfl_xor_sync(0xffffffffu, p, 2);

        float ex = __expf(p + beh);   // unnormalized softmax weight (scores bounded)

        if (chunk == 0)
            atomicAdd(g_sum + (size_t)t * 8 + h, ex);

        float* ap = g_agg + (size_t)t * 128 + i0;
        asm volatile("red.global.add.v4.f32 [%0], {%1,%2,%3,%4};"
                     :: "l"(ap), "f"(ex * V.x), "f"(ex * V.y),
                        "f"(ex * V.z), "f"(ex * V.w)
                     : "memory");
    }
}

// ----------------------------- K3: output GEMM -----------------------------
// out = (agg / (seg_sum + 1e-10)) @ Wo + bo ; normalization fused into A load.
__global__ void __launch_bounds__(256, 2) sgemm_out(
    const float* __restrict__ Wo, const float* __restrict__ bo,
    float* __restrict__ out, int M)
{
    __shared__ float As[8][128];
    __shared__ float Bs[8][128];

    const int tid  = threadIdx.x;
    const int tx   = tid & 15;
    const int ty   = tid >> 4;
    const int rowBase = blockIdx.x * 128;
    const int aRow = tid >> 1;
    const int aCol = (tid & 1) * 4;
    const int bRow = tid >> 5;
    const int bCol = (tid & 31) * 4;
    const int gRow = rowBase + aRow;
    const bool aValid = (gRow < M);
    const float* Aptr = g_agg + (size_t)gRow * 128;

    float acc[8][8];
#pragma unroll
    for (int i = 0; i < 8; i++)
#pragma unroll
        for (int j = 0; j < 8; j++) acc[i][j] = 0.f;

    for (int kk = 0; kk < 128; kk += 8) {
        float4 a4 = make_float4(0.f, 0.f, 0.f, 0.f);
        if (aValid) {
            a4 = *reinterpret_cast<const float4*>(Aptr + kk + aCol);
            int hh = (kk + aCol) >> 4;     // same head for all 4 lanes of the float4
            float sden = g_sum[(size_t)gRow * 8 + hh] + 1e-10f;
            float inv = 1.f / sden;
            a4.x *= inv; a4.y *= inv; a4.z *= inv; a4.w *= inv;
        }
        As[aCol + 0][aRow] = a4.x;
        As[aCol + 1][aRow] = a4.y;
        As[aCol + 2][aRow] = a4.z;
        As[aCol + 3][aRow] = a4.w;
        float4 b4 = *reinterpret_cast<const float4*>(Wo + (size_t)(kk + bRow) * 128 + bCol);
        *reinterpret_cast<float4*>(&Bs[bRow][bCol]) = b4;
        __syncthreads();
#pragma unroll
        for (int k = 0; k < 8; k++) {
            float4 a0 = *reinterpret_cast<const float4*>(&As[k][ty * 8]);
            float4 a1 = *reinterpret_cast<const float4*>(&As[k][ty * 8 + 4]);
            float4 b0 = *reinterpret_cast<const float4*>(&Bs[k][tx * 8]);
            float4 b1 = *reinterpret_cast<const float4*>(&Bs[k][tx * 8 + 4]);
            float ra[8] = {a0.x, a0.y, a0.z, a0.w, a1.x, a1.y, a1.z, a1.w};
            float rb[8] = {b0.x, b0.y, b0.z, b0.w, b1.x, b1.y, b1.z, b1.w};
#pragma unroll
            for (int i = 0; i < 8; i++)
#pragma unroll
                for (int j = 0; j < 8; j++)
                    acc[i][j] = fmaf(ra[i], rb[j], acc[i][j]);
        }
        __syncthreads();
    }

    float bv8[8];
#pragma unroll
    for (int j = 0; j < 8; j++) bv8[j] = bo[tx * 8 + j];

#pragma unroll
    for (int i = 0; i < 8; i++) {
        int row = rowBase + ty * 8 + i;
        if (row < M) {
            float* cp = out + (size_t)row * 128 + tx * 8;
            float4 o0 = make_float4(acc[i][0] + bv8[0], acc[i][1] + bv8[1],
                                    acc[i][2] + bv8[2], acc[i][3] + bv8[3]);
            float4 o1 = make_float4(acc[i][4] + bv8[4], acc[i][5] + bv8[5],
                                    acc[i][6] + bv8[6], acc[i][7] + bv8[7]);
            *reinterpret_cast<float4*>(cp)     = o0;
            *reinterpret_cast<float4*>(cp + 4) = o1;
        }
    }
}

// ------------------------------- launcher ----------------------------------
extern "C" void kernel_launch(void* const* d_in, const int* in_sizes, int n_in,
                              void* d_out, int out_size)
{
    const float* X  = (const float*)d_in[0];
    const int*   ei = (const int*)  d_in[1];
    const float* ef = (const float*)d_in[2];
    const float* Wl = (const float*)d_in[3];
    const float* bl = (const float*)d_in[4];
    const float* Wr = (const float*)d_in[5];
    const float* br = (const float*)d_in[6];
    const float* We = (const float*)d_in[7];
    const float* be = (const float*)d_in[8];
    const float* av = (const float*)d_in[9];
    const float* Wv = (const float*)d_in[10];
    const float* bv = (const float*)d_in[11];
    const float* Wo = (const float*)d_in[12];
    const float* bo = (const float*)d_in[13];

    int n_nodes = in_sizes[0] / IN_F;
    int E       = in_sizes[1] / 2;
    float* out  = (float*)d_out;

    zero_kernel<<<1024, 256>>>(n_nodes);

    dim3 g1((n_nodes + 127) / 128, 3);
    sgemm_proj<<<g1, 256>>>(X, Wl, bl, Wr, br, Wv, bv, n_nodes);

    edge_kernel<<<8192, 256>>>(ei, ef, We, be, av, E);

    dim3 g2((n_nodes + 127) / 128, 1);
    sgemm_out<<<g2, 256>>>(Wo, bo, out, n_nodes);
}

// round 5
// speedup vs baseline: 1.3576x; 1.3576x over previous
#include <cuda_runtime.h>
#include <cuda_bf16.h>
#include <cstdint>

// ---------------------------------------------------------------------------
// GATv2 layer:
//   K0 prep_kernel : zero agg/sum; transpose+bf16-split weights; pack biases
//   K1 gemm_mma<256,false> : proj[N,384] = X @ [Wl|Wr|Wv] + bias
//        warp-level mma.sync bf16 split-3 (hi*hi + hi*lo + lo*hi) ~fp32 accuracy
//   K2 edge_kernel : one pass: score -> exp -> unnormalized scatter aggregate
//   K3 gemm_mma<128,true>  : out = (agg / seg_sum) @ Wo + bo (norm fused in A)
// ---------------------------------------------------------------------------

#define N_MAX 50048
#define IN_F  256

__device__ __align__(16) float g_proj[(size_t)N_MAX * 384];
__device__ __align__(16) float g_agg [(size_t)N_MAX * 128];
__device__ __align__(16) float g_sum [(size_t)N_MAX * 8];

// bf16-split transposed weights: layout [band][n][k]  (B[n][k] = W[k][n])
__device__ __align__(16) __nv_bfloat16 g_Bhi_p[3 * 128 * 256];
__device__ __align__(16) __nv_bfloat16 g_Blo_p[3 * 128 * 256];
__device__ __align__(16) __nv_bfloat16 g_Bhi_o[128 * 128];
__device__ __align__(16) __nv_bfloat16 g_Blo_o[128 * 128];
__device__ __align__(16) float g_bias_p[384];

// ------------------------------ helpers ------------------------------------
__device__ __forceinline__ uint32_t s2u(const void* p) {
    uint32_t a;
    asm("{ .reg .u64 t; cvta.to.shared.u64 t, %1; cvt.u32.u64 %0, t; }"
        : "=r"(a) : "l"(p));
    return a;
}

__device__ __forceinline__ void ldmA(uint32_t* a, uint32_t addr) {
    asm volatile("ldmatrix.sync.aligned.m8n8.x4.shared.b16 {%0,%1,%2,%3}, [%4];"
                 : "=r"(a[0]), "=r"(a[1]), "=r"(a[2]), "=r"(a[3]) : "r"(addr));
}

__device__ __forceinline__ void mma16816(float* c, const uint32_t* a,
                                         uint32_t b0, uint32_t b1) {
    asm volatile(
        "mma.sync.aligned.m16n8k16.row.col.f32.bf16.bf16.f32 "
        "{%0,%1,%2,%3},{%4,%5,%6,%7},{%8,%9},{%0,%1,%2,%3};"
        : "+f"(c[0]), "+f"(c[1]), "+f"(c[2]), "+f"(c[3])
        : "r"(a[0]), "r"(a[1]), "r"(a[2]), "r"(a[3]), "r"(b0), "r"(b1));
}

// pack 2 floats -> hi bf16x2 (returned) + lo bf16x2 (out param)
__device__ __forceinline__ uint32_t pack2(float x, float y, uint32_t& lo) {
    __nv_bfloat16 hx = __float2bfloat16_rn(x);
    __nv_bfloat16 hy = __float2bfloat16_rn(y);
    __nv_bfloat16 lx = __float2bfloat16_rn(x - __bfloat162float(hx));
    __nv_bfloat16 ly = __float2bfloat16_rn(y - __bfloat162float(hy));
    lo = (uint32_t)__bfloat16_as_ushort(lx) | ((uint32_t)__bfloat16_as_ushort(ly) << 16);
    return (uint32_t)__bfloat16_as_ushort(hx) | ((uint32_t)__bfloat16_as_ushort(hy) << 16);
}

// ------------------------------- K0: prep ----------------------------------
__global__ void __launch_bounds__(256) prep_kernel(
    const float* __restrict__ Wl, const float* __restrict__ bl,
    const float* __restrict__ Wr, const float* __restrict__ br,
    const float* __restrict__ Wv, const float* __restrict__ bv,
    const float* __restrict__ Wo, int n_nodes)
{
    int idx0 = blockIdx.x * blockDim.x + threadIdx.x;
    int stride = gridDim.x * blockDim.x;

    float4 z = make_float4(0.f, 0.f, 0.f, 0.f);
    int nAgg4 = n_nodes * 32;
    for (int i = idx0; i < nAgg4; i += stride)
        reinterpret_cast<float4*>(g_agg)[i] = z;
    for (int i = idx0; i < n_nodes * 8; i += stride)
        g_sum[i] = 0.f;

    for (int i = idx0; i < 3 * 128 * 256; i += stride) {
        int band = i >> 15;
        int n = (i >> 8) & 127;
        int k = i & 255;
        const float* W = band == 0 ? Wl : (band == 1 ? Wr : Wv);
        float v = W[k * 128 + n];
        __nv_bfloat16 h = __float2bfloat16_rn(v);
        g_Bhi_p[i] = h;
        g_Blo_p[i] = __float2bfloat16_rn(v - __bfloat162float(h));
    }
    for (int i = idx0; i < 128 * 128; i += stride) {
        int n = i >> 7, k = i & 127;
        float v = Wo[k * 128 + n];
        __nv_bfloat16 h = __float2bfloat16_rn(v);
        g_Bhi_o[i] = h;
        g_Blo_o[i] = __float2bfloat16_rn(v - __bfloat162float(h));
    }
    for (int i = idx0; i < 384; i += stride)
        g_bias_p[i] = i < 128 ? bl[i] : (i < 256 ? br[i - 128] : bv[i - 256]);
}

// --------------------- K1/K3: warp-mma split-bf16 GEMM ---------------------
// CTA: 128x128 output tile, 256 threads = 8 warps in 4(m) x 2(n) grid,
// warp tile 32x64. K chunks of 64. Smem tiles stride 72 bf16 (=144B):
// row start bank group = 4*row mod 32 -> conflict-free ldmatrix phases and
// conflict-free 32-bit B-fragment loads (bank = 4g+tg, all distinct).
static constexpr int TSTRIDE = 72;                       // bf16 elems per smem row
static constexpr int TILE_B  = 128 * TSTRIDE * 2;        // 18432 B per tile
static constexpr int GEMM_SMEM = 4 * TILE_B;             // Ahi|Alo|Bhi|Blo = 72 KB

template<int KT, bool NORM>
__global__ void __launch_bounds__(256) gemm_mma(
    const float* __restrict__ Xin, const float* __restrict__ bias_in,
    float* __restrict__ out_in, int M)
{
    extern __shared__ char smem[];
    char* AHI = smem;
    char* ALO = smem + TILE_B;
    char* BHI = smem + 2 * TILE_B;
    char* BLO = smem + 3 * TILE_B;
    const uint32_t sAhi = s2u(AHI);
    const uint32_t sAlo = s2u(ALO);

    const int tid  = threadIdx.x;
    const int wid  = tid >> 5;
    const int lane = tid & 31;
    const int band = blockIdx.y;
    const int rowBase = blockIdx.x * 128;
    const int warpM = (wid & 3) * 32;
    const int warpN = (wid >> 2) * 64;
    const int g  = lane >> 2;       // group id
    const int tg = lane & 3;        // thread in group

    const float* A = NORM ? g_agg : Xin;
    const int lda = KT;
    const __nv_bfloat16* Bh = NORM ? g_Bhi_o : (g_Bhi_p + (size_t)band * 128 * 256);
    const __nv_bfloat16* Bl = NORM ? g_Blo_o : (g_Blo_p + (size_t)band * 128 * 256);
    const float* bias = NORM ? bias_in : g_bias_p;
    float* out = NORM ? out_in : g_proj;
    const int ostride = NORM ? 128 : 384;
    const int coloff = NORM ? 0 : band * 128;

    float acc[2][8][4];
#pragma unroll
    for (int mt = 0; mt < 2; mt++)
#pragma unroll
        for (int nt = 0; nt < 8; nt++)
#pragma unroll
            for (int j = 0; j < 4; j++) acc[mt][nt][j] = 0.f;

    // ldmatrix per-lane base address (row = warpM + (lane&7)+(lane&8), k = (lane>>4)*8)
    const uint32_t ldmOff =
        (uint32_t)(((warpM + (lane & 7) + (lane & 8)) * TSTRIDE + ((lane >> 4) << 3)) * 2);
    // B fragment base (uint32 index into the bf16 tile): n = warpN + g, k = tg*2
    const uint32_t bBase = (uint32_t)(((warpN + g) * TSTRIDE + tg * 2) >> 1);
    const uint32_t* BHu = reinterpret_cast<const uint32_t*>(BHI);
    const uint32_t* BLu = reinterpret_cast<const uint32_t*>(BLO);

    constexpr int NCH = KT / 64;
    for (int c = 0; c < NCH; c++) {
        const int kk = c * 64;

        // ---- A tile: global fp32 -> hi/lo bf16 smem ----
#pragma unroll
        for (int i = 0; i < 8; i++) {
            int flat = tid + i * 256;          // 2048 float4 slots
            int r = flat >> 4;
            int g4 = flat & 15;
            int m = rowBase + r;
            float4 a = make_float4(0.f, 0.f, 0.f, 0.f);
            if (m < M) {
                a = *reinterpret_cast<const float4*>(A + (size_t)m * lda + kk + g4 * 4);
                if (NORM) {
                    int hh = (kk + g4 * 4) >> 4;
                    float inv = 1.f / (g_sum[(size_t)m * 8 + hh] + 1e-10f);
                    a.x *= inv; a.y *= inv; a.z *= inv; a.w *= inv;
                }
            }
            uint2 hi, lo;
            hi.x = pack2(a.x, a.y, lo.x);
            hi.y = pack2(a.z, a.w, lo.y);
            int boff = r * (TSTRIDE * 2) + g4 * 8;
            *reinterpret_cast<uint2*>(AHI + boff) = hi;
            *reinterpret_cast<uint2*>(ALO + boff) = lo;
        }

        // ---- B tiles: prepped bf16 global -> smem ----
#pragma unroll
        for (int i = 0; i < 4; i++) {
            int flat = tid + i * 256;          // 1024 uint4 slots
            int n = flat >> 3;
            int grp = flat & 7;
            size_t soff = ((size_t)n * KT + kk + grp * 8) * 2;
            uint4 vh = *reinterpret_cast<const uint4*>(
                reinterpret_cast<const char*>(Bh) + soff);
            uint4 vl = *reinterpret_cast<const uint4*>(
                reinterpret_cast<const char*>(Bl) + soff);
            int boff = n * (TSTRIDE * 2) + grp * 16;
            *reinterpret_cast<uint4*>(BHI + boff) = vh;
            *reinterpret_cast<uint4*>(BLO + boff) = vl;
        }
        __syncthreads();

        // ---- MMA: 4 k16-steps x 3 split terms ----
#pragma unroll
        for (int k16 = 0; k16 < 4; k16++) {
            uint32_t ah[2][4], al[2][4];
            uint32_t ko = ldmOff + (uint32_t)(k16 * 16 * 2);
            ldmA(ah[0], sAhi + ko);
            ldmA(ah[1], sAhi + ko + (uint32_t)(16 * TSTRIDE * 2));
            ldmA(al[0], sAlo + ko);
            ldmA(al[1], sAlo + ko + (uint32_t)(16 * TSTRIDE * 2));
#pragma unroll
            for (int nt = 0; nt < 8; nt++) {
                uint32_t idx = bBase + (uint32_t)((nt * 8 * TSTRIDE + k16 * 16) >> 1);
                uint32_t bh0 = BHu[idx], bh1 = BHu[idx + 4];   // +8 bf16 = +4 u32
                uint32_t bl0 = BLu[idx], bl1 = BLu[idx + 4];
                mma16816(acc[0][nt], ah[0], bh0, bh1);
                mma16816(acc[1][nt], ah[1], bh0, bh1);
                mma16816(acc[0][nt], ah[0], bl0, bl1);
                mma16816(acc[1][nt], ah[1], bl0, bl1);
                mma16816(acc[0][nt], al[0], bh0, bh1);
                mma16816(acc[1][nt], al[1], bh0, bh1);
            }
        }
        __syncthreads();
    }

    // ---- epilogue ----
#pragma unroll
    for (int mt = 0; mt < 2; mt++) {
        int r0 = rowBase + warpM + mt * 16 + g;
#pragma unroll
        for (int nt = 0; nt < 8; nt++) {
            int col = coloff + warpN + nt * 8 + tg * 2;
            float b0 = bias[col], b1 = bias[col + 1];
            if (r0 < M) {
                float2 v = make_float2(acc[mt][nt][0] + b0, acc[mt][nt][1] + b1);
                *reinterpret_cast<float2*>(out + (size_t)r0 * ostride + col) = v;
            }
            if (r0 + 8 < M) {
                float2 v = make_float2(acc[mt][nt][2] + b0, acc[mt][nt][3] + b1);
                *reinterpret_cast<float2*>(out + (size_t)(r0 + 8) * ostride + col) = v;
            }
        }
    }
}

// ------------------------------ K2: edge pass ------------------------------
__global__ void __launch_bounds__(256) edge_kernel(
    const int*   __restrict__ ei, const float* __restrict__ ef,
    const float* __restrict__ We, const float* __restrict__ be,
    const float* __restrict__ av, int E)
{
    const int tid   = threadIdx.x;
    const int lane  = tid & 31;
    const int h     = lane >> 2;
    const int chunk = lane & 3;
    const int i0    = lane << 2;

    float4 A4 = *reinterpret_cast<const float4*>(av + i0);
    float beh = be[h];
    float w[16];
#pragma unroll
    for (int j = 0; j < 16; j++)
        w[j] = We[(chunk * 16 + j) * 8 + h];

    int gw = (blockIdx.x * 256 + tid) >> 5;
    int nw = (gridDim.x * 256) >> 5;

    for (int e = gw; e < E; e += nw) {
        int s = __ldg(ei + e);
        int t = __ldg(ei + E + e);
        const float* baseT = g_proj + (size_t)t * 384;
        const float* baseS = g_proj + (size_t)s * 384;
        float4 L = *reinterpret_cast<const float4*>(baseT + i0);
        float4 R = *reinterpret_cast<const float4*>(baseS + 128 + i0);
        float4 V = *reinterpret_cast<const float4*>(baseS + 256 + i0);
        const float4* pe = reinterpret_cast<const float4*>(ef + (size_t)e * 64 + chunk * 16);
        float4 e0 = __ldg(pe + 0);
        float4 e1 = __ldg(pe + 1);
        float4 e2 = __ldg(pe + 2);
        float4 e3 = __ldg(pe + 3);

        float cx = L.x + R.x; cx = cx > 0.f ? cx : 0.2f * cx;
        float cy = L.y + R.y; cy = cy > 0.f ? cy : 0.2f * cy;
        float cz = L.z + R.z; cz = cz > 0.f ? cz : 0.2f * cz;
        float cw = L.w + R.w; cw = cw > 0.f ? cw : 0.2f * cw;
        float p = cx * A4.x + cy * A4.y + cz * A4.z + cw * A4.w;

        p = fmaf(e0.x, w[0],  p); p = fmaf(e0.y, w[1],  p);
        p = fmaf(e0.z, w[2],  p); p = fmaf(e0.w, w[3],  p);
        p = fmaf(e1.x, w[4],  p); p = fmaf(e1.y, w[5],  p);
        p = fmaf(e1.z, w[6],  p); p = fmaf(e1.w, w[7],  p);
        p = fmaf(e2.x, w[8],  p); p = fmaf(e2.y, w[9],  p);
        p = fmaf(e2.z, w[10], p); p = fmaf(e2.w, w[11], p);
        p = fmaf(e3.x, w[12], p); p = fmaf(e3.y, w[13], p);
        p = fmaf(e3.z, w[14], p); p = fmaf(e3.w, w[15], p);

        p += __shfl_xor_sync(0xffffffffu, p, 1);
        p += __shfl_xor_sync(0xffffffffu, p, 2);

        float ex = __expf(p + beh);

        if (chunk == 0)
            atomicAdd(g_sum + (size_t)t * 8 + h, ex);

        float* ap = g_agg + (size_t)t * 128 + i0;
        asm volatile("red.global.add.v4.f32 [%0], {%1,%2,%3,%4};"
                     :: "l"(ap), "f"(ex * V.x), "f"(ex * V.y),
                        "f"(ex * V.z), "f"(ex * V.w)
                     : "memory");
    }
}

// ------------------------------- launcher ----------------------------------
extern "C" void kernel_launch(void* const* d_in, const int* in_sizes, int n_in,
                              void* d_out, int out_size)
{
    const float* X  = (const float*)d_in[0];
    const int*   ei = (const int*)  d_in[1];
    const float* ef = (const float*)d_in[2];
    const float* Wl = (const float*)d_in[3];
    const float* bl = (const float*)d_in[4];
    const float* Wr = (const float*)d_in[5];
    const float* br = (const float*)d_in[6];
    const float* We = (const float*)d_in[7];
    const float* be = (const float*)d_in[8];
    const float* av = (const float*)d_in[9];
    const float* Wv = (const float*)d_in[10];
    const float* bv = (const float*)d_in[11];
    const float* Wo = (const float*)d_in[12];
    const float* bo = (const float*)d_in[13];

    int n_nodes = in_sizes[0] / IN_F;
    int E       = in_sizes[1] / 2;
    float* out  = (float*)d_out;

    cudaFuncSetAttribute(gemm_mma<256, false>,
                         cudaFuncAttributeMaxDynamicSharedMemorySize, GEMM_SMEM);
    cudaFuncSetAttribute(gemm_mma<128, true>,
                         cudaFuncAttributeMaxDynamicSharedMemorySize, GEMM_SMEM);

    prep_kernel<<<2048, 256>>>(Wl, bl, Wr, br, Wv, bv, Wo, n_nodes);

    dim3 g1((n_nodes + 127) / 128, 3);
    gemm_mma<256, false><<<g1, 256, GEMM_SMEM>>>(X, nullptr, nullptr, n_nodes);

    edge_kernel<<<8192, 256>>>(ei, ef, We, be, av, E);

    dim3 g2((n_nodes + 127) / 128, 1);
    gemm_mma<128, true><<<g2, 256, GEMM_SMEM>>>(nullptr, bo, out, n_nodes);
}

// round 6
// speedup vs baseline: 1.5242x; 1.1227x over previous
#include <cuda_runtime.h>
#include <cuda_bf16.h>
#include <cstdint>

// ---------------------------------------------------------------------------
// GATv2 layer:
//   K0 prep_kernel   : zero agg/sum; split weights AND X into hi/lo bf16
//   K1 gemm_async<256,true>  : proj[N,384] = X @ [Wl|Wr|Wv] + bias
//        2-stage cp.async pipeline, warp mma.sync bf16 split-3 (~fp32 accuracy)
//   K2 edge_kernel   : one pass: score -> exp -> unnormalized scatter aggregate
//        (next-iteration index prefetch hides index-load latency)
//   K3 normalize     : agg/sum -> hi/lo bf16
//   K4 gemm_async<128,false> : out = norm_agg @ Wo + bo
// ---------------------------------------------------------------------------

#define N_MAX 50048
#define IN_F  256

__device__ __align__(16) float g_proj[(size_t)N_MAX * 384];
__device__ __align__(16) float g_agg [(size_t)N_MAX * 128];
__device__ __align__(16) float g_sum [(size_t)N_MAX * 8];

// bf16-split operands
__device__ __align__(16) __nv_bfloat16 g_Xhi[(size_t)N_MAX * 256];
__device__ __align__(16) __nv_bfloat16 g_Xlo[(size_t)N_MAX * 256];
__device__ __align__(16) __nv_bfloat16 g_Ahi_o[(size_t)N_MAX * 128];
__device__ __align__(16) __nv_bfloat16 g_Alo_o[(size_t)N_MAX * 128];
// transposed weights [band][n][k] (B[n][k] = W[k][n])
__device__ __align__(16) __nv_bfloat16 g_Bhi_p[3 * 128 * 256];
__device__ __align__(16) __nv_bfloat16 g_Blo_p[3 * 128 * 256];
__device__ __align__(16) __nv_bfloat16 g_Bhi_o[128 * 128];
__device__ __align__(16) __nv_bfloat16 g_Blo_o[128 * 128];
__device__ __align__(16) float g_bias_p[384];

// ------------------------------ helpers ------------------------------------
__device__ __forceinline__ uint32_t s2u(const void* p) {
    uint32_t a;
    asm("{ .reg .u64 t; cvta.to.shared.u64 t, %1; cvt.u32.u64 %0, t; }"
        : "=r"(a) : "l"(p));
    return a;
}

__device__ __forceinline__ void cpa16(uint32_t dst, const void* src) {
    asm volatile("cp.async.cg.shared.global [%0], [%1], 16;"
                 :: "r"(dst), "l"(src));
}

__device__ __forceinline__ void ldmA(uint32_t* a, uint32_t addr) {
    asm volatile("ldmatrix.sync.aligned.m8n8.x4.shared.b16 {%0,%1,%2,%3}, [%4];"
                 : "=r"(a[0]), "=r"(a[1]), "=r"(a[2]), "=r"(a[3]) : "r"(addr));
}

__device__ __forceinline__ void mma16816(float* c, const uint32_t* a,
                                         uint32_t b0, uint32_t b1) {
    asm volatile(
        "mma.sync.aligned.m16n8k16.row.col.f32.bf16.bf16.f32 "
        "{%0,%1,%2,%3},{%4,%5,%6,%7},{%8,%9},{%0,%1,%2,%3};"
        : "+f"(c[0]), "+f"(c[1]), "+f"(c[2]), "+f"(c[3])
        : "r"(a[0]), "r"(a[1]), "r"(a[2]), "r"(a[3]), "r"(b0), "r"(b1));
}

// pack 2 floats -> hi bf16x2 (returned) + lo bf16x2 (out param)
__device__ __forceinline__ uint32_t pack2(float x, float y, uint32_t& lo) {
    __nv_bfloat16 hx = __float2bfloat16_rn(x);
    __nv_bfloat16 hy = __float2bfloat16_rn(y);
    __nv_bfloat16 lx = __float2bfloat16_rn(x - __bfloat162float(hx));
    __nv_bfloat16 ly = __float2bfloat16_rn(y - __bfloat162float(hy));
    lo = (uint32_t)__bfloat16_as_ushort(lx) | ((uint32_t)__bfloat16_as_ushort(ly) << 16);
    return (uint32_t)__bfloat16_as_ushort(hx) | ((uint32_t)__bfloat16_as_ushort(hy) << 16);
}

// ------------------------------- K0: prep ----------------------------------
__global__ void __launch_bounds__(256) prep_kernel(
    const float* __restrict__ X,
    const float* __restrict__ Wl, const float* __restrict__ bl,
    const float* __restrict__ Wr, const float* __restrict__ br,
    const float* __restrict__ Wv, const float* __restrict__ bv,
    const float* __restrict__ Wo, int n_nodes)
{
    int idx0 = blockIdx.x * blockDim.x + threadIdx.x;
    int stride = gridDim.x * blockDim.x;

    float4 z = make_float4(0.f, 0.f, 0.f, 0.f);
    int nAgg4 = n_nodes * 32;
    for (int i = idx0; i < nAgg4; i += stride)
        reinterpret_cast<float4*>(g_agg)[i] = z;
    for (int i = idx0; i < n_nodes * 8; i += stride)
        g_sum[i] = 0.f;

    // split X (vectorized: 2 floats -> one bf16x2 hi + one lo word)
    int nX2 = n_nodes * 128;     // pairs
    for (int i = idx0; i < nX2; i += stride) {
        float2 v = reinterpret_cast<const float2*>(X)[i];
        uint32_t lo;
        uint32_t hi = pack2(v.x, v.y, lo);
        reinterpret_cast<uint32_t*>(g_Xhi)[i] = hi;
        reinterpret_cast<uint32_t*>(g_Xlo)[i] = lo;
    }

    for (int i = idx0; i < 3 * 128 * 256; i += stride) {
        int band = i >> 15;
        int n = (i >> 8) & 127;
        int k = i & 255;
        const float* W = band == 0 ? Wl : (band == 1 ? Wr : Wv);
        float v = W[k * 128 + n];
        __nv_bfloat16 h = __float2bfloat16_rn(v);
        g_Bhi_p[i] = h;
        g_Blo_p[i] = __float2bfloat16_rn(v - __bfloat162float(h));
    }
    for (int i = idx0; i < 128 * 128; i += stride) {
        int n = i >> 7, k = i & 127;
        float v = Wo[k * 128 + n];
        __nv_bfloat16 h = __float2bfloat16_rn(v);
        g_Bhi_o[i] = h;
        g_Blo_o[i] = __float2bfloat16_rn(v - __bfloat162float(h));
    }
    for (int i = idx0; i < 384; i += stride)
        g_bias_p[i] = i < 128 ? bl[i] : (i < 256 ? br[i - 128] : bv[i - 256]);
}

// ---------------- K1/K4: cp.async 2-stage split-bf16 MMA GEMM --------------
// CTA: 128x128 tile, 8 warps (4m x 2n), warp tile 32x64. K-chunk 32.
// Smem tiles: 128 rows x 40 bf16 stride (80B). Bank-conflict-free for
// ldmatrix (row bank 20r mod 32) and B-fragment LDS.32 (20g+tg, 32 distinct).
// 2 stages x 4 tiles x 10240B = 80KB -> 2 CTAs/SM; load(c+1) overlaps MMA(c).
static constexpr int TSTRIDE = 40;                 // bf16 per smem row
static constexpr int TILE_B  = 128 * TSTRIDE * 2;  // 10240 B
static constexpr int STAGE_B = 4 * TILE_B;         // 40960 B
static constexpr int GEMM_SMEM = 2 * STAGE_B;      // 81920 B

template<int KT, bool PROJ>
__global__ void __launch_bounds__(256, 2) gemm_async(
    const float* __restrict__ bias_ext, float* __restrict__ out_ext, int M)
{
    constexpr int NCH = KT / 32;
    extern __shared__ char smem[];
    const uint32_t sb = s2u(smem);

    const int tid  = threadIdx.x;
    const int wid  = tid >> 5;
    const int lane = tid & 31;
    const int band = blockIdx.y;
    const int rowBase = blockIdx.x * 128;
    const int warpM = (wid & 3) * 32;
    const int warpN = (wid >> 2) * 64;
    const int g  = lane >> 2;
    const int tg = lane & 3;

    const __nv_bfloat16* Ah = PROJ ? g_Xhi : g_Ahi_o;
    const __nv_bfloat16* Al = PROJ ? g_Xlo : g_Alo_o;
    const __nv_bfloat16* Bh = PROJ ? (g_Bhi_p + (size_t)band * 128 * 256) : g_Bhi_o;
    const __nv_bfloat16* Bl = PROJ ? (g_Blo_p + (size_t)band * 128 * 256) : g_Blo_o;
    const float* bias = PROJ ? g_bias_p : bias_ext;
    float* out = PROJ ? g_proj : out_ext;
    const int ostride = PROJ ? 384 : 128;
    const int coloff  = PROJ ? band * 128 : 0;

    // per-thread cp.async slots: flat = tid + i*256, r=flat>>2, g2=flat&3
    const int r0c  = tid >> 2;
    const int g2c  = tid & 3;
    const uint32_t dst0 = sb + (uint32_t)(r0c * 80 + g2c * 16);
    const size_t aoff0 = ((size_t)(rowBase + r0c) * KT) * 2 + g2c * 16;
    const size_t boff0 = ((size_t)r0c * KT) * 2 + g2c * 16;

    float acc[2][8][4];
#pragma unroll
    for (int mt = 0; mt < 2; mt++)
#pragma unroll
        for (int nt = 0; nt < 8; nt++)
#pragma unroll
            for (int j = 0; j < 4; j++) acc[mt][nt][j] = 0.f;

    const uint32_t ldmOff =
        (uint32_t)(((warpM + (lane & 7) + (lane & 8)) * TSTRIDE + ((lane >> 4) << 3)) * 2);
    const uint32_t bBase = (uint32_t)((warpN + g) * (TSTRIDE / 2) + tg);

    auto issue = [&](int c, int s) {
        const size_t kb = (size_t)(c * 32) * 2;   // byte offset of chunk in K
        const uint32_t so = (uint32_t)(s * STAGE_B);
#pragma unroll
        for (int i = 0; i < 2; i++) {
            const uint32_t d = dst0 + so + (uint32_t)(i * 64 * 80);
            const size_t ao = aoff0 + kb + (size_t)i * 64 * KT * 2;
            const size_t bo = boff0 + kb + (size_t)i * 64 * KT * 2;
            cpa16(d,              (const char*)Ah + ao);
            cpa16(d + TILE_B,     (const char*)Al + ao);
            cpa16(d + 2 * TILE_B, (const char*)Bh + bo);
            cpa16(d + 3 * TILE_B, (const char*)Bl + bo);
        }
        asm volatile("cp.async.commit_group;");
    };

    issue(0, 0);
#pragma unroll
    for (int c = 0; c < NCH; c++) {
        if (c + 1 < NCH) {
            issue(c + 1, (c + 1) & 1);
            asm volatile("cp.async.wait_group 1;");
        } else {
            asm volatile("cp.async.wait_group 0;");
        }
        __syncthreads();

        const uint32_t so = (uint32_t)((c & 1) * STAGE_B);
        const uint32_t sAhi = sb + so;
        const uint32_t sAlo = sAhi + TILE_B;
        const uint32_t* BHu = reinterpret_cast<const uint32_t*>(smem + (c & 1) * STAGE_B + 2 * TILE_B);
        const uint32_t* BLu = reinterpret_cast<const uint32_t*>(smem + (c & 1) * STAGE_B + 3 * TILE_B);

#pragma unroll
        for (int k16 = 0; k16 < 2; k16++) {
            uint32_t ah[2][4], al[2][4];
            uint32_t ko = ldmOff + (uint32_t)(k16 * 32);
            ldmA(ah[0], sAhi + ko);
            ldmA(ah[1], sAhi + ko + (uint32_t)(16 * TSTRIDE * 2));
            ldmA(al[0], sAlo + ko);
            ldmA(al[1], sAlo + ko + (uint32_t)(16 * TSTRIDE * 2));
#pragma unroll
            for (int nt = 0; nt < 8; nt++) {
                uint32_t idx = bBase + (uint32_t)(nt * 8 * (TSTRIDE / 2) + k16 * 8);
                uint32_t bh0 = BHu[idx], bh1 = BHu[idx + 4];
                uint32_t bl0 = BLu[idx], bl1 = BLu[idx + 4];
                mma16816(acc[0][nt], ah[0], bh0, bh1);
                mma16816(acc[1][nt], ah[1], bh0, bh1);
                mma16816(acc[0][nt], ah[0], bl0, bl1);
                mma16816(acc[1][nt], ah[1], bl0, bl1);
                mma16816(acc[0][nt], al[0], bh0, bh1);
                mma16816(acc[1][nt], al[1], bh0, bh1);
            }
        }
        __syncthreads();
    }

    // ---- epilogue ----
#pragma unroll
    for (int mt = 0; mt < 2; mt++) {
        int r0 = rowBase + warpM + mt * 16 + g;
#pragma unroll
        for (int nt = 0; nt < 8; nt++) {
            int col = coloff + warpN + nt * 8 + tg * 2;
            float b0 = bias[col], b1 = bias[col + 1];
            if (r0 < M) {
                float2 v = make_float2(acc[mt][nt][0] + b0, acc[mt][nt][1] + b1);
                *reinterpret_cast<float2*>(out + (size_t)r0 * ostride + col) = v;
            }
            if (r0 + 8 < M) {
                float2 v = make_float2(acc[mt][nt][2] + b0, acc[mt][nt][3] + b1);
                *reinterpret_cast<float2*>(out + (size_t)(r0 + 8) * ostride + col) = v;
            }
        }
    }
}

// ------------------------------ K2: edge pass ------------------------------
__global__ void __launch_bounds__(256) edge_kernel(
    const int*   __restrict__ ei, const float* __restrict__ ef,
    const float* __restrict__ We, const float* __restrict__ be,
    const float* __restrict__ av, int E)
{
    const int tid   = threadIdx.x;
    const int lane  = tid & 31;
    const int h     = lane >> 2;
    const int chunk = lane & 3;
    const int i0    = lane << 2;

    float4 A4 = *reinterpret_cast<const float4*>(av + i0);
    float beh = be[h];
    float w[16];
#pragma unroll
    for (int j = 0; j < 16; j++)
        w[j] = We[(chunk * 16 + j) * 8 + h];

    int gw = (blockIdx.x * 256 + tid) >> 5;
    int nw = (gridDim.x * 256) >> 5;

    // prefetch first iteration's indices (removes 600-cyc index load from
    // the gather dependency chain of every iteration)
    int sN = 0, tN = 0;
    if (gw < E) { sN = __ldg(ei + gw); tN = __ldg(ei + E + gw); }

    for (int e = gw; e < E; e += nw) {
        int s = sN, t = tN;
        int en = e + nw;
        if (en < E) { sN = __ldg(ei + en); tN = __ldg(ei + E + en); }

        const float* baseT = g_proj + (size_t)t * 384;
        const float* baseS = g_proj + (size_t)s * 384;
        float4 L = *reinterpret_cast<const float4*>(baseT + i0);
        float4 R = *reinterpret_cast<const float4*>(baseS + 128 + i0);
        float4 V = *reinterpret_cast<const float4*>(baseS + 256 + i0);
        const float4* pe = reinterpret_cast<const float4*>(ef + (size_t)e * 64 + chunk * 16);
        float4 e0 = __ldg(pe + 0);
        float4 e1 = __ldg(pe + 1);
        float4 e2 = __ldg(pe + 2);
        float4 e3 = __ldg(pe + 3);

        float cx = L.x + R.x; cx = cx > 0.f ? cx : 0.2f * cx;
        float cy = L.y + R.y; cy = cy > 0.f ? cy : 0.2f * cy;
        float cz = L.z + R.z; cz = cz > 0.f ? cz : 0.2f * cz;
        float cw = L.w + R.w; cw = cw > 0.f ? cw : 0.2f * cw;
        float p = cx * A4.x + cy * A4.y + cz * A4.z + cw * A4.w;

        p = fmaf(e0.x, w[0],  p); p = fmaf(e0.y, w[1],  p);
        p = fmaf(e0.z, w[2],  p); p = fmaf(e0.w, w[3],  p);
        p = fmaf(e1.x, w[4],  p); p = fmaf(e1.y, w[5],  p);
        p = fmaf(e1.z, w[6],  p); p = fmaf(e1.w, w[7],  p);
        p = fmaf(e2.x, w[8],  p); p = fmaf(e2.y, w[9],  p);
        p = fmaf(e2.z, w[10], p); p = fmaf(e2.w, w[11], p);
        p = fmaf(e3.x, w[12], p); p = fmaf(e3.y, w[13], p);
        p = fmaf(e3.z, w[14], p); p = fmaf(e3.w, w[15], p);

        p += __shfl_xor_sync(0xffffffffu, p, 1);
        p += __shfl_xor_sync(0xffffffffu, p, 2);

        float ex = __expf(p + beh);

        if (chunk == 0)
            atomicAdd(g_sum + (size_t)t * 8 + h, ex);

        float* ap = g_agg + (size_t)t * 128 + i0;
        asm volatile("red.global.add.v4.f32 [%0], {%1,%2,%3,%4};"
                     :: "l"(ap), "f"(ex * V.x), "f"(ex * V.y),
                        "f"(ex * V.z), "f"(ex * V.w)
                     : "memory");
    }
}

// --------------------- K3: normalize agg -> bf16 split ---------------------
__global__ void __launch_bounds__(256) normalize_kernel(int Mpad) {
    int idx = blockIdx.x * blockDim.x + threadIdx.x;
    int stride = gridDim.x * blockDim.x;
    int total = Mpad * 32;   // 128 floats per row in float4 groups
    for (int i = idx; i < total; i += stride) {
        int n = i >> 5, g4 = i & 31;
        float4 a = *reinterpret_cast<const float4*>(g_agg + (size_t)n * 128 + g4 * 4);
        float inv = 1.f / (g_sum[(size_t)n * 8 + (g4 >> 2)] + 1e-10f);
        a.x *= inv; a.y *= inv; a.z *= inv; a.w *= inv;
        uint2 hi, lo;
        hi.x = pack2(a.x, a.y, lo.x);
        hi.y = pack2(a.z, a.w, lo.y);
        *reinterpret_cast<uint2*>(reinterpret_cast<char*>(g_Ahi_o) + (size_t)n * 256 + g4 * 8) = hi;
        *reinterpret_cast<uint2*>(reinterpret_cast<char*>(g_Alo_o) + (size_t)n * 256 + g4 * 8) = lo;
    }
}

// ------------------------------- launcher ----------------------------------
extern "C" void kernel_launch(void* const* d_in, const int* in_sizes, int n_in,
                              void* d_out, int out_size)
{
    const float* X  = (const float*)d_in[0];
    const int*   ei = (const int*)  d_in[1];
    const float* ef = (const float*)d_in[2];
    const float* Wl = (const float*)d_in[3];
    const float* bl = (const float*)d_in[4];
    const float* Wr = (const float*)d_in[5];
    const float* br = (const float*)d_in[6];
    const float* We = (const float*)d_in[7];
    const float* be = (const float*)d_in[8];
    const float* av = (const float*)d_in[9];
    const float* Wv = (const float*)d_in[10];
    const float* bv = (const float*)d_in[11];
    const float* Wo = (const float*)d_in[12];
    const float* bo = (const float*)d_in[13];

    int n_nodes = in_sizes[0] / IN_F;
    int E       = in_sizes[1] / 2;
    float* out  = (float*)d_out;
    int nBlocks = (n_nodes + 127) / 128;
    int Mpad    = nBlocks * 128;

    cudaFuncSetAttribute(gemm_async<256, true>,
                         cudaFuncAttributeMaxDynamicSharedMemorySize, GEMM_SMEM);
    cudaFuncSetAttribute(gemm_async<128, false>,
                         cudaFuncAttributeMaxDynamicSharedMemorySize, GEMM_SMEM);

    prep_kernel<<<2048, 256>>>(X, Wl, bl, Wr, br, Wv, bv, Wo, n_nodes);

    dim3 g1(nBlocks, 3);
    gemm_async<256, true><<<g1, 256, GEMM_SMEM>>>(nullptr, nullptr, n_nodes);

    edge_kernel<<<8192, 256>>>(ei, ef, We, be, av, E);

    normalize_kernel<<<1024, 256>>>(Mpad);

    dim3 g2(nBlocks, 1);
    gemm_async<128, false><<<g2, 256, GEMM_SMEM>>>(bo, out, n_nodes);
}

// round 9
// speedup vs baseline: 1.6319x; 1.0707x over previous
#include <cuda_runtime.h>
#include <cuda_bf16.h>
#include <cstdint>

// ---------------------------------------------------------------------------
// GATv2 layer:
//   K0 prep_kernel   : zero agg/sum; split weights AND X into hi/lo bf16
//   K1 gemm_async<256,true>  : [L|R] bf16 + V fp32 = X @ [Wl|Wr|Wv] + bias
//        2-stage cp.async pipeline, warp mma.sync bf16 split-3 (~fp32 accuracy)
//   K2 edge_kernel   : one pass over edges; L/R bf16 + V fp32 gathers,
//                      streaming (evict-first) ef loads
//   K3 normalize     : agg/sum -> hi/lo bf16
//   K4 gemm_async<128,false> : out = norm_agg @ Wo + bo  (fp32 out)
// ---------------------------------------------------------------------------

#define N_MAX 50048
#define IN_F  256

__device__ __align__(16) float g_agg [(size_t)N_MAX * 128];
__device__ __align__(16) float g_sum [(size_t)N_MAX * 8];

// edge-pass operands (written by proj GEMM epilogue)
__device__ __align__(16) __nv_bfloat16 g_edgeLR[(size_t)N_MAX * 256]; // [n][L 0:128|R 128:256]
__device__ __align__(16) float         g_valf  [(size_t)N_MAX * 128]; // V fp32 (precision!)

// bf16-split GEMM operands
__device__ __align__(16) __nv_bfloat16 g_Xhi[(size_t)N_MAX * 256];
__device__ __align__(16) __nv_bfloat16 g_Xlo[(size_t)N_MAX * 256];
__device__ __align__(16) __nv_bfloat16 g_Ahi_o[(size_t)N_MAX * 128];
__device__ __align__(16) __nv_bfloat16 g_Alo_o[(size_t)N_MAX * 128];
// transposed weights [band][n][k] (B[n][k] = W[k][n])
__device__ __align__(16) __nv_bfloat16 g_Bhi_p[3 * 128 * 256];
__device__ __align__(16) __nv_bfloat16 g_Blo_p[3 * 128 * 256];
__device__ __align__(16) __nv_bfloat16 g_Bhi_o[128 * 128];
__device__ __align__(16) __nv_bfloat16 g_Blo_o[128 * 128];
__device__ __align__(16) float g_bias_p[384];

// ------------------------------ helpers ------------------------------------
__device__ __forceinline__ uint32_t s2u(const void* p) {
    uint32_t a;
    asm("{ .reg .u64 t; cvta.to.shared.u64 t, %1; cvt.u32.u64 %0, t; }"
        : "=r"(a) : "l"(p));
    return a;
}

__device__ __forceinline__ void cpa16(uint32_t dst, const void* src) {
    asm volatile("cp.async.cg.shared.global [%0], [%1], 16;"
                 :: "r"(dst), "l"(src));
}

__device__ __forceinline__ void ldmA(uint32_t* a, uint32_t addr) {
    asm volatile("ldmatrix.sync.aligned.m8n8.x4.shared.b16 {%0,%1,%2,%3}, [%4];"
                 : "=r"(a[0]), "=r"(a[1]), "=r"(a[2]), "=r"(a[3]) : "r"(addr));
}

__device__ __forceinline__ void mma16816(float* c, const uint32_t* a,
                                         uint32_t b0, uint32_t b1) {
    asm volatile(
        "mma.sync.aligned.m16n8k16.row.col.f32.bf16.bf16.f32 "
        "{%0,%1,%2,%3},{%4,%5,%6,%7},{%8,%9},{%0,%1,%2,%3};"
        : "+f"(c[0]), "+f"(c[1]), "+f"(c[2]), "+f"(c[3])
        : "r"(a[0]), "r"(a[1]), "r"(a[2]), "r"(a[3]), "r"(b0), "r"(b1));
}

// streaming fp32x4 load (ld.global.cs: evict-first policy, portable)
__device__ __forceinline__ float4 ldg_stream4(const float4* p) {
    return __ldcs(p);
}

// pack 2 floats -> hi bf16x2 (returned) + lo bf16x2 (out param)
__device__ __forceinline__ uint32_t pack2(float x, float y, uint32_t& lo) {
    __nv_bfloat16 hx = __float2bfloat16_rn(x);
    __nv_bfloat16 hy = __float2bfloat16_rn(y);
    __nv_bfloat16 lx = __float2bfloat16_rn(x - __bfloat162float(hx));
    __nv_bfloat16 ly = __float2bfloat16_rn(y - __bfloat162float(hy));
    lo = (uint32_t)__bfloat16_as_ushort(lx) | ((uint32_t)__bfloat16_as_ushort(ly) << 16);
    return (uint32_t)__bfloat16_as_ushort(hx) | ((uint32_t)__bfloat16_as_ushort(hy) << 16);
}

// ------------------------------- K0: prep ----------------------------------
__global__ void __launch_bounds__(256) prep_kernel(
    const float* __restrict__ X,
    const float* __restrict__ Wl, const float* __restrict__ bl,
    const float* __restrict__ Wr, const float* __restrict__ br,
    const float* __restrict__ Wv, const float* __restrict__ bv,
    const float* __restrict__ Wo, int n_nodes)
{
    int idx0 = blockIdx.x * blockDim.x + threadIdx.x;
    int stride = gridDim.x * blockDim.x;

    float4 z = make_float4(0.f, 0.f, 0.f, 0.f);
    int nAgg4 = n_nodes * 32;
    for (int i = idx0; i < nAgg4; i += stride)
        reinterpret_cast<float4*>(g_agg)[i] = z;
    for (int i = idx0; i < n_nodes * 8; i += stride)
        g_sum[i] = 0.f;

    int nX2 = n_nodes * 128;     // float pairs
    for (int i = idx0; i < nX2; i += stride) {
        float2 v = reinterpret_cast<const float2*>(X)[i];
        uint32_t lo;
        uint32_t hi = pack2(v.x, v.y, lo);
        reinterpret_cast<uint32_t*>(g_Xhi)[i] = hi;
        reinterpret_cast<uint32_t*>(g_Xlo)[i] = lo;
    }

    for (int i = idx0; i < 3 * 128 * 256; i += stride) {
        int band = i >> 15;
        int n = (i >> 8) & 127;
        int k = i & 255;
        const float* W = band == 0 ? Wl : (band == 1 ? Wr : Wv);
        float v = W[k * 128 + n];
        __nv_bfloat16 h = __float2bfloat16_rn(v);
        g_Bhi_p[i] = h;
        g_Blo_p[i] = __float2bfloat16_rn(v - __bfloat162float(h));
    }
    for (int i = idx0; i < 128 * 128; i += stride) {
        int n = i >> 7, k = i & 127;
        float v = Wo[k * 128 + n];
        __nv_bfloat16 h = __float2bfloat16_rn(v);
        g_Bhi_o[i] = h;
        g_Blo_o[i] = __float2bfloat16_rn(v - __bfloat162float(h));
    }
    for (int i = idx0; i < 384; i += stride)
        g_bias_p[i] = i < 128 ? bl[i] : (i < 256 ? br[i - 128] : bv[i - 256]);
}

// ---------------- K1/K4: cp.async 2-stage split-bf16 MMA GEMM --------------
// CTA: 128x128 tile, 8 warps (4m x 2n), warp tile 32x64. K-chunk 32.
// Smem stride 40 bf16 (80B): conflict-free ldmatrix + B-fragment LDS.32.
// 80KB smem -> 2 CTAs/SM, load(c+1) overlaps MMA(c).
static constexpr int TSTRIDE = 40;
static constexpr int TILE_B  = 128 * TSTRIDE * 2;  // 10240 B
static constexpr int STAGE_B = 4 * TILE_B;         // 40960 B
static constexpr int GEMM_SMEM = 2 * STAGE_B;      // 81920 B

template<int KT, bool PROJ>
__global__ void __launch_bounds__(256, 2) gemm_async(
    const float* __restrict__ bias_ext, float* __restrict__ out_ext, int M)
{
    constexpr int NCH = KT / 32;
    extern __shared__ char smem[];
    const uint32_t sb = s2u(smem);

    const int tid  = threadIdx.x;
    const int wid  = tid >> 5;
    const int lane = tid & 31;
    const int band = blockIdx.y;
    const int rowBase = blockIdx.x * 128;
    const int warpM = (wid & 3) * 32;
    const int warpN = (wid >> 2) * 64;
    const int g  = lane >> 2;
    const int tg = lane & 3;

    const __nv_bfloat16* Ah = PROJ ? g_Xhi : g_Ahi_o;
    const __nv_bfloat16* Al = PROJ ? g_Xlo : g_Alo_o;
    const __nv_bfloat16* Bh = PROJ ? (g_Bhi_p + (size_t)band * 128 * 256) : g_Bhi_o;
    const __nv_bfloat16* Bl = PROJ ? (g_Blo_p + (size_t)band * 128 * 256) : g_Blo_o;

    const int r0c  = tid >> 2;
    const int g2c  = tid & 3;
    const uint32_t dst0 = sb + (uint32_t)(r0c * 80 + g2c * 16);
    const size_t aoff0 = ((size_t)(rowBase + r0c) * KT) * 2 + g2c * 16;
    const size_t boff0 = ((size_t)r0c * KT) * 2 + g2c * 16;

    float acc[2][8][4];
#pragma unroll
    for (int mt = 0; mt < 2; mt++)
#pragma unroll
        for (int nt = 0; nt < 8; nt++)
#pragma unroll
            for (int j = 0; j < 4; j++) acc[mt][nt][j] = 0.f;

    const uint32_t ldmOff =
        (uint32_t)(((warpM + (lane & 7) + (lane & 8)) * TSTRIDE + ((lane >> 4) << 3)) * 2);
    const uint32_t bBase = (uint32_t)((warpN + g) * (TSTRIDE / 2) + tg);

    auto issue = [&](int c, int s) {
        const size_t kb = (size_t)(c * 32) * 2;
        const uint32_t so = (uint32_t)(s * STAGE_B);
#pragma unroll
        for (int i = 0; i < 2; i++) {
            const uint32_t d = dst0 + so + (uint32_t)(i * 64 * 80);
            const size_t ao = aoff0 + kb + (size_t)i * 64 * KT * 2;
            const size_t bo = boff0 + kb + (size_t)i * 64 * KT * 2;
            cpa16(d,              (const char*)Ah + ao);
            cpa16(d + TILE_B,     (const char*)Al + ao);
            cpa16(d + 2 * TILE_B, (const char*)Bh + bo);
            cpa16(d + 3 * TILE_B, (const char*)Bl + bo);
        }
        asm volatile("cp.async.commit_group;");
    };

    issue(0, 0);
#pragma unroll
    for (int c = 0; c < NCH; c++) {
        if (c + 1 < NCH) {
            issue(c + 1, (c + 1) & 1);
            asm volatile("cp.async.wait_group 1;");
        } else {
            asm volatile("cp.async.wait_group 0;");
        }
        __syncthreads();

        const uint32_t so = (uint32_t)((c & 1) * STAGE_B);
        const uint32_t sAhi = sb + so;
        const uint32_t sAlo = sAhi + TILE_B;
        const uint32_t* BHu = reinterpret_cast<const uint32_t*>(smem + (c & 1) * STAGE_B + 2 * TILE_B);
        const uint32_t* BLu = reinterpret_cast<const uint32_t*>(smem + (c & 1) * STAGE_B + 3 * TILE_B);

#pragma unroll
        for (int k16 = 0; k16 < 2; k16++) {
            uint32_t ah[2][4], al[2][4];
            uint32_t ko = ldmOff + (uint32_t)(k16 * 32);
            ldmA(ah[0], sAhi + ko);
            ldmA(ah[1], sAhi + ko + (uint32_t)(16 * TSTRIDE * 2));
            ldmA(al[0], sAlo + ko);
            ldmA(al[1], sAlo + ko + (uint32_t)(16 * TSTRIDE * 2));
#pragma unroll
            for (int nt = 0; nt < 8; nt++) {
                uint32_t idx = bBase + (uint32_t)(nt * 8 * (TSTRIDE / 2) + k16 * 8);
                uint32_t bh0 = BHu[idx], bh1 = BHu[idx + 4];
                uint32_t bl0 = BLu[idx], bl1 = BLu[idx + 4];
                mma16816(acc[0][nt], ah[0], bh0, bh1);
                mma16816(acc[1][nt], ah[1], bh0, bh1);
                mma16816(acc[0][nt], ah[0], bl0, bl1);
                mma16816(acc[1][nt], ah[1], bl0, bl1);
                mma16816(acc[0][nt], al[0], bh0, bh1);
                mma16816(acc[1][nt], al[1], bh0, bh1);
            }
        }
        __syncthreads();
    }

    // ---- epilogue ----
    if (PROJ) {
        if (band == 2) {
            // V band -> fp32 (precision-critical: output magnitude shrinks
            // ~4x through softmax averaging, inflating V quantization error)
#pragma unroll
            for (int mt = 0; mt < 2; mt++) {
                int r0 = rowBase + warpM + mt * 16 + g;
#pragma unroll
                for (int nt = 0; nt < 8; nt++) {
                    int col = warpN + nt * 8 + tg * 2;
                    float b0 = g_bias_p[256 + col], b1 = g_bias_p[256 + col + 1];
                    if (r0 < M) {
                        float2 v = make_float2(acc[mt][nt][0] + b0, acc[mt][nt][1] + b1);
                        *reinterpret_cast<float2*>(g_valf + (size_t)r0 * 128 + col) = v;
                    }
                    if (r0 + 8 < M) {
                        float2 v = make_float2(acc[mt][nt][2] + b0, acc[mt][nt][3] + b1);
                        *reinterpret_cast<float2*>(g_valf + (size_t)(r0 + 8) * 128 + col) = v;
                    }
                }
            }
        } else {
            // L/R bands -> bf16 (score path: abs error ~8e-5, negligible)
#pragma unroll
            for (int mt = 0; mt < 2; mt++) {
                int r0 = rowBase + warpM + mt * 16 + g;
#pragma unroll
                for (int nt = 0; nt < 8; nt++) {
                    int col = warpN + nt * 8 + tg * 2;
                    float b0 = g_bias_p[band * 128 + col];
                    float b1 = g_bias_p[band * 128 + col + 1];
                    if (r0 < M) {
                        __nv_bfloat162 h = __floats2bfloat162_rn(acc[mt][nt][0] + b0,
                                                                 acc[mt][nt][1] + b1);
                        *reinterpret_cast<__nv_bfloat162*>(
                            g_edgeLR + (size_t)r0 * 256 + band * 128 + col) = h;
                    }
                    if (r0 + 8 < M) {
                        __nv_bfloat162 h = __floats2bfloat162_rn(acc[mt][nt][2] + b0,
                                                                 acc[mt][nt][3] + b1);
                        *reinterpret_cast<__nv_bfloat162*>(
                            g_edgeLR + (size_t)(r0 + 8) * 256 + band * 128 + col) = h;
                    }
                }
            }
        }
    } else {
#pragma unroll
        for (int mt = 0; mt < 2; mt++) {
            int r0 = rowBase + warpM + mt * 16 + g;
#pragma unroll
            for (int nt = 0; nt < 8; nt++) {
                int col = warpN + nt * 8 + tg * 2;
                float b0 = bias_ext[col], b1 = bias_ext[col + 1];
                if (r0 < M) {
                    float2 v = make_float2(acc[mt][nt][0] + b0, acc[mt][nt][1] + b1);
                    *reinterpret_cast<float2*>(out_ext + (size_t)r0 * 128 + col) = v;
                }
                if (r0 + 8 < M) {
                    float2 v = make_float2(acc[mt][nt][2] + b0, acc[mt][nt][3] + b1);
                    *reinterpret_cast<float2*>(out_ext + (size_t)(r0 + 8) * 128 + col) = v;
                }
            }
        }
    }
}

// ------------------------------ K2: edge pass ------------------------------
// Warp per edge. Lane owns 4 of the 128 dims (head h = lane>>2).
// L/R gathered bf16 (8B/lane), V fp32 (16B/lane), ef streamed (ld.global.cs).
__global__ void __launch_bounds__(256) edge_kernel(
    const int*   __restrict__ ei, const float* __restrict__ ef,
    const float* __restrict__ We, const float* __restrict__ be,
    const float* __restrict__ av, int E)
{
    const int tid   = threadIdx.x;
    const int lane  = tid & 31;
    const int h     = lane >> 2;
    const int chunk = lane & 3;
    const int i0    = lane << 2;

    float4 A4 = *reinterpret_cast<const float4*>(av + i0);
    float beh = be[h];
    float w[16];
#pragma unroll
    for (int j = 0; j < 16; j++)
        w[j] = We[(chunk * 16 + j) * 8 + h];

    int gw = (blockIdx.x * 256 + tid) >> 5;
    int nw = (gridDim.x * 256) >> 5;

    int sN = 0, tN = 0;
    if (gw < E) { sN = __ldg(ei + gw); tN = __ldg(ei + E + gw); }

    for (int e = gw; e < E; e += nw) {
        int s = sN, t = tN;
        int en = e + nw;
        if (en < E) { sN = __ldg(ei + en); tN = __ldg(ei + E + en); }

        const __nv_bfloat162* Lp =
            reinterpret_cast<const __nv_bfloat162*>(g_edgeLR + (size_t)t * 256 + i0);
        const __nv_bfloat162* Rp =
            reinterpret_cast<const __nv_bfloat162*>(g_edgeLR + (size_t)s * 256 + 128 + i0);
        __nv_bfloat162 Lb0 = Lp[0], Lb1 = Lp[1];
        __nv_bfloat162 Rb0 = Rp[0], Rb1 = Rp[1];
        float4 V = *reinterpret_cast<const float4*>(g_valf + (size_t)s * 128 + i0);
        const float4* pe = reinterpret_cast<const float4*>(ef + (size_t)e * 64 + chunk * 16);
        float4 e0 = ldg_stream4(pe + 0);
        float4 e1 = ldg_stream4(pe + 1);
        float4 e2 = ldg_stream4(pe + 2);
        float4 e3 = ldg_stream4(pe + 3);

        float2 L01 = __bfloat1622float2(Lb0), L23 = __bfloat1622float2(Lb1);
        float2 R01 = __bfloat1622float2(Rb0), R23 = __bfloat1622float2(Rb1);

        float cx = L01.x + R01.x; cx = cx > 0.f ? cx : 0.2f * cx;
        float cy = L01.y + R01.y; cy = cy > 0.f ? cy : 0.2f * cy;
        float cz = L23.x + R23.x; cz = cz > 0.f ? cz : 0.2f * cz;
        float cw = L23.y + R23.y; cw = cw > 0.f ? cw : 0.2f * cw;
        float p = cx * A4.x + cy * A4.y + cz * A4.z + cw * A4.w;

        p = fmaf(e0.x, w[0],  p); p = fmaf(e0.y, w[1],  p);
        p = fmaf(e0.z, w[2],  p); p = fmaf(e0.w, w[3],  p);
        p = fmaf(e1.x, w[4],  p); p = fmaf(e1.y, w[5],  p);
        p = fmaf(e1.z, w[6],  p); p = fmaf(e1.w, w[7],  p);
        p = fmaf(e2.x, w[8],  p); p = fmaf(e2.y, w[9],  p);
        p = fmaf(e2.z, w[10], p); p = fmaf(e2.w, w[11], p);
        p = fmaf(e3.x, w[12], p); p = fmaf(e3.y, w[13], p);
        p = fmaf(e3.z, w[14], p); p = fmaf(e3.w, w[15], p);

        p += __shfl_xor_sync(0xffffffffu, p, 1);
        p += __shfl_xor_sync(0xffffffffu, p, 2);

        float ex = __expf(p + beh);

        if (chunk == 0)
            atomicAdd(g_sum + (size_t)t * 8 + h, ex);

        float* ap = g_agg + (size_t)t * 128 + i0;
        asm volatile("red.global.add.v4.f32 [%0], {%1,%2,%3,%4};"
                     :: "l"(ap), "f"(ex * V.x), "f"(ex * V.y),
                        "f"(ex * V.z), "f"(ex * V.w)
                     : "memory");
    }
}

// --------------------- K3: normalize agg -> bf16 split ---------------------
__global__ void __launch_bounds__(256) normalize_kernel(int Mpad) {
    int idx = blockIdx.x * blockDim.x + threadIdx.x;
    int stride = gridDim.x * blockDim.x;
    int total = Mpad * 32;
    for (int i = idx; i < total; i += stride) {
        int n = i >> 5, g4 = i & 31;
        float4 a = *reinterpret_cast<const float4*>(g_agg + (size_t)n * 128 + g4 * 4);
        float inv = 1.f / (g_sum[(size_t)n * 8 + (g4 >> 2)] + 1e-10f);
        a.x *= inv; a.y *= inv; a.z *= inv; a.w *= inv;
        uint2 hi, lo;
        hi.x = pack2(a.x, a.y, lo.x);
        hi.y = pack2(a.z, a.w, lo.y);
        *reinterpret_cast<uint2*>(reinterpret_cast<char*>(g_Ahi_o) + (size_t)n * 256 + g4 * 8) = hi;
        *reinterpret_cast<uint2*>(reinterpret_cast<char*>(g_Alo_o) + (size_t)n * 256 + g4 * 8) = lo;
    }
}

// ------------------------------- launcher ----------------------------------
extern "C" void kernel_launch(void* const* d_in, const int* in_sizes, int n_in,
                              void* d_out, int out_size)
{
    const float* X  = (const float*)d_in[0];
    const int*   ei = (const int*)  d_in[1];
    const float* ef = (const float*)d_in[2];
    const float* Wl = (const float*)d_in[3];
    const float* bl = (const float*)d_in[4];
    const float* Wr = (const float*)d_in[5];
    const float* br = (const float*)d_in[6];
    const float* We = (const float*)d_in[7];
    const float* be = (const float*)d_in[8];
    const float* av = (const float*)d_in[9];
    const float* Wv = (const float*)d_in[10];
    const float* bv = (const float*)d_in[11];
    const float* Wo = (const float*)d_in[12];
    const float* bo = (const float*)d_in[13];

    int n_nodes = in_sizes[0] / IN_F;
    int E       = in_sizes[1] / 2;
    float* out  = (float*)d_out;
    int nBlocks = (n_nodes + 127) / 128;
    int Mpad    = nBlocks * 128;

    cudaFuncSetAttribute(gemm_async<256, true>,
                         cudaFuncAttributeMaxDynamicSharedMemorySize, GEMM_SMEM);
    cudaFuncSetAttribute(gemm_async<128, false>,
                         cudaFuncAttributeMaxDynamicSharedMemorySize, GEMM_SMEM);

    prep_kernel<<<2048, 256>>>(X, Wl, bl, Wr, br, Wv, bv, Wo, n_nodes);

    dim3 g1(nBlocks, 3);
    gemm_async<256, true><<<g1, 256, GEMM_SMEM>>>(nullptr, nullptr, n_nodes);

    edge_kernel<<<8192, 256>>>(ei, ef, We, be, av, E);

    normalize_kernel<<<1024, 256>>>(Mpad);

    dim3 g2(nBlocks, 1);
    gemm_async<128, false><<<g2, 256, GEMM_SMEM>>>(bo, out, n_nodes);
}